// round 1
// baseline (speedup 1.0000x reference)
#include <cuda_runtime.h>

#define SLOPE 0.1f
#define LFRM  1024
#define CHANS 144
#define WINL  32
#define NWIN  993                 // (1024 - 32)/1 + 1
#define MROWS (NWIN*CHANS)        // 142992
#define NTHR  256

// scratch (no cudaMalloc allowed)
__device__ float g_d6[LFRM*CHANS];        // 1024 x 144
__device__ float g_y[MROWS*WINL];         // per-window outputs, [m][w]

__device__ __forceinline__ float lrelu(float x){ return x >= 0.0f ? x : SLOPE*x; }

// ---------------------------------------------------------------------------
// Stage A: axis-angle -> rotation matrix -> 6D (first two rows)
// ---------------------------------------------------------------------------
__global__ void aa_to_d6_kernel(const float* __restrict__ dp){
    int idx = blockIdx.x*blockDim.x + threadIdx.x;
    if (idx >= LFRM*24) return;
    int t = idx/24, j = idx - 24*t;
    float x = dp[t*72+3*j], y = dp[t*72+3*j+1], z = dp[t*72+3*j+2];
    float ang = sqrtf(x*x + y*y + z*z);
    float inv = 1.0f / fmaxf(ang, 1e-8f);
    x *= inv; y *= inv; z *= inv;
    float s = sinf(ang), c = cosf(ang);
    float C = 1.0f - c;
    float* o = g_d6 + t*CHANS + 6*j;
    o[0] = c + x*x*C;      o[1] = x*y*C - z*s;   o[2] = x*z*C + y*s;
    o[3] = y*x*C + z*s;    o[4] = c + y*y*C;     o[5] = y*z*C - x*s;
}

// ---------------------------------------------------------------------------
// Main MLP kernel helpers
// Weight chunk loader: stage W[n][k0..k0+31] (row-major [N][KF]) into
// wb[kk][n] with row stride N+1 (conflict-free STS and B-reads).
// ---------------------------------------------------------------------------
template<int NW, int KF>
__device__ __forceinline__ void load_wchunk(const float* __restrict__ W, int k0,
                                            float* __restrict__ wb){
    const int STR = NW + 1;
    for (int e = threadIdx.x; e < NW*8; e += NTHR){
        int n = e >> 3, u = e & 7;
        float4 v = *reinterpret_cast<const float4*>(W + n*KF + k0 + 4*u);
        int base = (4*u)*STR + n;
        wb[base        ] = v.x;
        wb[base +   STR] = v.y;
        wb[base + 2*STR] = v.z;
        wb[base + 3*STR] = v.w;
    }
}

// One K-chunk of C[32][NW] += A[32][K] * W^T.  Thread (tr,tc): rows 4tr..4tr+3,
// cols tc+32*j.  A reads are warp-broadcast (tr uniform per warp), vectorized.
template<int TN, int NW>
__device__ __forceinline__ void mma_chunk(const float* __restrict__ A, int astr, int k0,
                                          const float* __restrict__ wb,
                                          float (&acc)[4][TN], int tr, int tc){
    const int STR = NW + 1;
    const float* a0 = A + (4*tr)*astr + k0;
    #pragma unroll
    for (int k4 = 0; k4 < 32; k4 += 4){
        float4 v0 = *reinterpret_cast<const float4*>(a0 +           k4);
        float4 v1 = *reinterpret_cast<const float4*>(a0 +   astr +  k4);
        float4 v2 = *reinterpret_cast<const float4*>(a0 + 2*astr +  k4);
        float4 v3 = *reinterpret_cast<const float4*>(a0 + 3*astr +  k4);
        const float* br = wb + k4*STR + tc;
        #pragma unroll
        for (int j = 0; j < TN; j++){ float b = br[32*j];
            acc[0][j] += v0.x*b; acc[1][j] += v1.x*b; acc[2][j] += v2.x*b; acc[3][j] += v3.x*b; }
        br += STR;
        #pragma unroll
        for (int j = 0; j < TN; j++){ float b = br[32*j];
            acc[0][j] += v0.y*b; acc[1][j] += v1.y*b; acc[2][j] += v2.y*b; acc[3][j] += v3.y*b; }
        br += STR;
        #pragma unroll
        for (int j = 0; j < TN; j++){ float b = br[32*j];
            acc[0][j] += v0.z*b; acc[1][j] += v1.z*b; acc[2][j] += v2.z*b; acc[3][j] += v3.z*b; }
        br += STR;
        #pragma unroll
        for (int j = 0; j < TN; j++){ float b = br[32*j];
            acc[0][j] += v0.w*b; acc[1][j] += v1.w*b; acc[2][j] += v2.w*b; acc[3][j] += v3.w*b; }
    }
}

// One residual block: rs = lrelu(hs @ wa^T + ba); hs += lrelu(rs @ wbm^T + bb)
__device__ __forceinline__ void resblock(float* hs, float* rs, float* wb,
    const float* __restrict__ wa,  const float* __restrict__ ba,
    const float* __restrict__ wbm, const float* __restrict__ bb,
    int tr, int tc)
{
    {   // 32x512 @ 512x256
        float acc[4][8];
        #pragma unroll
        for (int i=0;i<4;i++){
            #pragma unroll
            for (int j=0;j<8;j++) acc[i][j] = 0.0f;
        }
        for (int k0 = 0; k0 < 512; k0 += 32){
            __syncthreads();
            load_wchunk<256,512>(wa, k0, wb);
            __syncthreads();
            mma_chunk<8,256>(hs, 512, k0, wb, acc, tr, tc);
        }
        #pragma unroll
        for (int j=0;j<8;j++){
            float bv = ba[tc + 32*j];
            #pragma unroll
            for (int i=0;i<4;i++)
                rs[(4*tr+i)*256 + tc + 32*j] = lrelu(acc[i][j] + bv);
        }
    }
    {   // 32x256 @ 256x512, residual add into hs
        float acc[4][16];
        #pragma unroll
        for (int i=0;i<4;i++){
            #pragma unroll
            for (int j=0;j<16;j++) acc[i][j] = 0.0f;
        }
        for (int k0 = 0; k0 < 256; k0 += 32){
            __syncthreads();
            load_wchunk<512,256>(wbm, k0, wb);
            __syncthreads();
            mma_chunk<16,512>(rs, 256, k0, wb, acc, tr, tc);
        }
        #pragma unroll
        for (int j=0;j<16;j++){
            float bv = bb[tc + 32*j];
            #pragma unroll
            for (int i=0;i<4;i++){
                int off = (4*tr+i)*512 + tc + 32*j;
                hs[off] = hs[off] + lrelu(acc[i][j] + bv);
            }
        }
    }
}

// ---------------------------------------------------------------------------
// Main kernel: 32 (window,channel) rows per CTA, full MLP chain in SMEM.
// ---------------------------------------------------------------------------
__global__ void __launch_bounds__(NTHR, 1)
main_kernel(const float* __restrict__ w_in, const float* __restrict__ b_in,
            const float* __restrict__ w1a, const float* __restrict__ b1a,
            const float* __restrict__ w1b, const float* __restrict__ b1b,
            const float* __restrict__ w2a, const float* __restrict__ b2a,
            const float* __restrict__ w2b, const float* __restrict__ b2b,
            const float* __restrict__ w_out, const float* __restrict__ b_out)
{
    extern __shared__ float smf[];
    float* xs = smf;               // 32*36  = 1152 floats (stride 36, 16B aligned rows)
    float* hs = smf + 1152;        // 32*512 = 16384
    float* rs = hs + 16384;        // 32*256 = 8192
    float* wb = rs + 8192;         // 32*513 = 16416
    int tid = threadIdx.x, tr = tid >> 5, tc = tid & 31;
    int m0 = blockIdx.x * 32;

    // load x window tile: xs[r][t] = d6[n+t][c] for m = m0+r
    for (int e = tid; e < 32*32; e += NTHR){
        int rrow = e & 31, t = e >> 5;
        int m = m0 + rrow; if (m >= MROWS) m = MROWS - 1;
        int n = m / CHANS, c = m - n*CHANS;
        xs[rrow*36 + t] = g_d6[(n + t)*CHANS + c];
    }

    // GEMM1: hs = lrelu(xs(32x32) @ w_in^T(32->512) + b_in)
    {
        float acc[4][16];
        #pragma unroll
        for (int i=0;i<4;i++){
            #pragma unroll
            for (int j=0;j<16;j++) acc[i][j] = 0.0f;
        }
        __syncthreads();
        load_wchunk<512,32>(w_in, 0, wb);
        __syncthreads();
        mma_chunk<16,512>(xs, 36, 0, wb, acc, tr, tc);
        #pragma unroll
        for (int j=0;j<16;j++){
            float bv = b_in[tc + 32*j];
            #pragma unroll
            for (int i=0;i<4;i++)
                hs[(4*tr+i)*512 + tc + 32*j] = lrelu(acc[i][j] + bv);
        }
    }

    resblock(hs, rs, wb, w1a, b1a, w1b, b1b, tr, tc);
    resblock(hs, rs, wb, w2a, b2a, w2b, b2b, tr, tc);

    // GEMM6: y = hs(32x512) @ w_out^T(512->32) + b_out  -> g_y
    {
        float acc[4][1];
        acc[0][0]=acc[1][0]=acc[2][0]=acc[3][0]=0.0f;
        for (int k0 = 0; k0 < 512; k0 += 32){
            __syncthreads();
            load_wchunk<32,512>(w_out, k0, wb);
            __syncthreads();
            mma_chunk<1,32>(hs, 512, k0, wb, acc, tr, tc);
        }
        float bv = b_out[tc];
        #pragma unroll
        for (int i=0;i<4;i++){
            int m = m0 + 4*tr + i;
            if (m < MROWS) g_y[m*WINL + tc] = acc[i][0] + bv;
        }
    }
}

// ---------------------------------------------------------------------------
// Stage C: overlap-average + 6D -> rotation matrix -> axis-angle
// ---------------------------------------------------------------------------
__global__ void finalize_kernel(float* __restrict__ out){
    int idx = blockIdx.x*blockDim.x + threadIdx.x;
    if (idx >= LFRM*24) return;
    int t = idx/24, j = idx - 24*t;
    int lo = t - 31; if (lo < 0) lo = 0;
    int hi = t;      if (hi > NWIN-1) hi = NWIN-1;
    float s0=0,s1=0,s2=0,s3=0,s4=0,s5=0;
    for (int n = lo; n <= hi; n++){
        const float* yy = g_y + (n*CHANS + 6*j)*WINL + (t - n);
        s0 += yy[0];      s1 += yy[WINL];   s2 += yy[2*WINL];
        s3 += yy[3*WINL]; s4 += yy[4*WINL]; s5 += yy[5*WINL];
    }
    float inv = 1.0f / (float)(hi - lo + 1);
    float a1x=s0*inv, a1y=s1*inv, a1z=s2*inv;
    float a2x=s3*inv, a2y=s4*inv, a2z=s5*inv;
    float n1 = sqrtf(a1x*a1x + a1y*a1y + a1z*a1z);
    float i1 = 1.0f / fmaxf(n1, 1e-8f);
    float b1x=a1x*i1, b1y=a1y*i1, b1z=a1z*i1;
    float d = b1x*a2x + b1y*a2y + b1z*a2z;
    float px = a2x - d*b1x, py = a2y - d*b1y, pz = a2z - d*b1z;
    float n2 = sqrtf(px*px + py*py + pz*pz);
    float i2 = 1.0f / fmaxf(n2, 1e-8f);
    float b2x=px*i2, b2y=py*i2, b2z=pz*i2;
    float b3x = b1y*b2z - b1z*b2y;
    float b3y = b1z*b2x - b1x*b2z;
    float b3z = b1x*b2y - b1y*b2x;
    float trc  = b1x + b2y + b3z;
    float cosv = (trc - 1.0f)*0.5f;
    cosv = fminf(fmaxf(cosv, -1.0f + 1e-6f), 1.0f - 1e-6f);
    float ang  = acosf(cosv);
    float sinv = sqrtf(fmaxf(1.0f - cosv*cosv, 1e-12f));
    float sc   = ang / (2.0f*sinv);
    out[t*72 + 3*j    ] = sc*(b3y - b2z);   // R21 - R12
    out[t*72 + 3*j + 1] = sc*(b1z - b3x);   // R02 - R20
    out[t*72 + 3*j + 2] = sc*(b2x - b1y);   // R10 - R01
}

// ---------------------------------------------------------------------------
extern "C" void kernel_launch(void* const* d_in, const int* in_sizes, int n_in,
                              void* d_out, int out_size){
    const float* dp    = (const float*)d_in[0];
    const float* w_in  = (const float*)d_in[1];
    const float* b_in  = (const float*)d_in[2];
    const float* w1a   = (const float*)d_in[3];
    const float* b1a   = (const float*)d_in[4];
    const float* w1b   = (const float*)d_in[5];
    const float* b1b   = (const float*)d_in[6];
    const float* w2a   = (const float*)d_in[7];
    const float* b2a   = (const float*)d_in[8];
    const float* w2b   = (const float*)d_in[9];
    const float* b2b   = (const float*)d_in[10];
    const float* w_out = (const float*)d_in[11];
    const float* b_out = (const float*)d_in[12];
    float* out = (float*)d_out;

    const int SMEM = (1152 + 16384 + 8192 + 16416) * 4;  // 168576 B
    cudaFuncSetAttribute(main_kernel, cudaFuncAttributeMaxDynamicSharedMemorySize, SMEM);

    aa_to_d6_kernel<<<(LFRM*24 + 255)/256, 256>>>(dp);
    main_kernel<<<(MROWS + 31)/32, NTHR, SMEM>>>(w_in, b_in, w1a, b1a, w1b, b1b,
                                                 w2a, b2a, w2b, b2b, w_out, b_out);
    finalize_kernel<<<(LFRM*24 + 255)/256, 256>>>(out);
}

// round 2
// speedup vs baseline: 1.1737x; 1.1737x over previous
#include <cuda_runtime.h>

#define SLOPE 0.1f
#define LFRM  1024
#define CHANS 144
#define WINL  32
#define NWIN  993                 // (1024 - 32)/1 + 1
#define MROWS (NWIN*CHANS)        // 142992
#define NTHR  256

typedef unsigned long long ull;

// scratch (no cudaMalloc allowed)
__device__ float g_d6[LFRM*CHANS];        // 1024 x 144
__device__ float g_y[MROWS*WINL];         // per-window outputs, [m][w]

__device__ __forceinline__ float lrelu(float x){ return x >= 0.0f ? x : SLOPE*x; }

// packed f32x2 helpers (Blackwell FFMA2 path)
__device__ __forceinline__ void fma2(ull& d, ull a, ull b){
    asm("fma.rn.f32x2 %0, %1, %2, %0;" : "+l"(d) : "l"(a), "l"(b));
}
__device__ __forceinline__ ull dup2(float x){
    ull r; asm("mov.b64 %0, {%1, %1};" : "=l"(r) : "f"(x)); return r;
}
__device__ __forceinline__ float2 u2f(ull v){
    float2 f; asm("mov.b64 {%0, %1}, %2;" : "=f"(f.x), "=f"(f.y) : "l"(v)); return f;
}

// ---------------------------------------------------------------------------
// Stage A: axis-angle -> rotation matrix -> 6D (first two rows)
// ---------------------------------------------------------------------------
__global__ void aa_to_d6_kernel(const float* __restrict__ dp){
    int idx = blockIdx.x*blockDim.x + threadIdx.x;
    if (idx >= LFRM*24) return;
    int t = idx/24, j = idx - 24*t;
    float x = dp[t*72+3*j], y = dp[t*72+3*j+1], z = dp[t*72+3*j+2];
    float ang = sqrtf(x*x + y*y + z*z);
    float inv = 1.0f / fmaxf(ang, 1e-8f);
    x *= inv; y *= inv; z *= inv;
    float s = sinf(ang), c = cosf(ang);
    float C = 1.0f - c;
    float* o = g_d6 + t*CHANS + 6*j;
    o[0] = c + x*x*C;      o[1] = x*y*C - z*s;   o[2] = x*z*C + y*s;
    o[3] = y*x*C + z*s;    o[4] = c + y*y*C;     o[5] = y*z*C - x*s;
}

// ---------------------------------------------------------------------------
// Weight staging: W row-major [N][KF] -> wb k-major [32][NW+2]
// (transpose; pairs of adjacent n are 8B-aligned for LDS.64 f32x2 operands)
// ---------------------------------------------------------------------------
template<int NW, int KF>
__device__ __forceinline__ void stage_w(const float* __restrict__ W, int k0,
                                        float* __restrict__ wb){
    const int NWP = NW + 2;
    for (int e = threadIdx.x; e < NW*8; e += NTHR){
        int n = e >> 3, u = e & 7;
        float4 v = *reinterpret_cast<const float4*>(W + n*KF + k0 + 4*u);
        wb[(4*u  )*NWP + n] = v.x;
        wb[(4*u+1)*NWP + n] = v.y;
        wb[(4*u+2)*NWP + n] = v.z;
        wb[(4*u+3)*NWP + n] = v.w;
    }
}

// ---------------------------------------------------------------------------
// One K=32 chunk of C[32][NW] += A[32][32] @ Wchunk^T with packed FFMA2.
// acc[i][j] is f32x2 over adjacent output columns (2p, 2p+1), p = pbase+32j.
// Rows r0..r0+RPT-1 per thread (processed in groups of <=8 to bound regs).
// ---------------------------------------------------------------------------
template<int RPT, int PPT, int NW>
__device__ __forceinline__ void mma_cp(const float* __restrict__ A, int astr,
                                       const float* __restrict__ wb,
                                       ull (&acc)[RPT][PPT], int r0, int pbase){
    const int NWP = NW + 2;
    constexpr int GR = RPT < 8 ? RPT : 8;
    #pragma unroll
    for (int h = 0; h < RPT/GR; h++){
        const float* a0 = A + (r0 + GR*h)*astr;
        #pragma unroll
        for (int k4 = 0; k4 < 32; k4 += 4){
            float4 av[GR];
            #pragma unroll
            for (int i = 0; i < GR; i++)
                av[i] = *reinterpret_cast<const float4*>(a0 + i*astr + k4);
            #pragma unroll
            for (int kk = 0; kk < 4; kk++){
                const ull* bp = reinterpret_cast<const ull*>(wb + (k4+kk)*NWP);
                ull b[PPT];
                #pragma unroll
                for (int j = 0; j < PPT; j++) b[j] = bp[pbase + 32*j];
                #pragma unroll
                for (int i = 0; i < GR; i++){
                    float as = (kk==0) ? av[i].x : (kk==1) ? av[i].y
                             : (kk==2) ? av[i].z : av[i].w;
                    ull ad = dup2(as);
                    #pragma unroll
                    for (int j = 0; j < PPT; j++) fma2(acc[GR*h+i][j], ad, b[j]);
                }
            }
        }
    }
}

// One residual block: rs = lrelu(hs @ wa^T + ba); hs += lrelu(rs @ wbm^T + bb)
__device__ __forceinline__ void resblock(float* hs, float* rs, float* wb,
    const float* __restrict__ wa,  const float* __restrict__ ba,
    const float* __restrict__ wbm, const float* __restrict__ bb,
    int r0, int wc, int tc)
{
    {   // 32x512 @ (256x512)^T -> rs 32x256,  PPT=1
        int pbase = tc + 32*wc;
        ull acc[16][1];
        #pragma unroll
        for (int i=0;i<16;i++) acc[i][0] = 0ull;
        for (int k0 = 0; k0 < 512; k0 += 32){
            __syncthreads();
            stage_w<256,512>(wa, k0, wb);
            __syncthreads();
            mma_cp<16,1,256>(hs + k0, 512, wb, acc, r0, pbase);
        }
        float2 bv = *reinterpret_cast<const float2*>(ba + 2*pbase);
        #pragma unroll
        for (int i=0;i<16;i++){
            float2 a = u2f(acc[i][0]);
            *reinterpret_cast<float2*>(rs + (r0+i)*256 + 2*pbase) =
                make_float2(lrelu(a.x + bv.x), lrelu(a.y + bv.y));
        }
    }
    {   // 32x256 @ (512x256)^T -> residual into hs 32x512,  PPT=2
        int pbase = tc + 64*wc;
        ull acc[16][2];
        #pragma unroll
        for (int i=0;i<16;i++){ acc[i][0] = 0ull; acc[i][1] = 0ull; }
        for (int k0 = 0; k0 < 256; k0 += 32){
            __syncthreads();
            stage_w<512,256>(wbm, k0, wb);
            __syncthreads();
            mma_cp<16,2,512>(rs + k0, 256, wb, acc, r0, pbase);
        }
        #pragma unroll
        for (int j=0;j<2;j++){
            int p = pbase + 32*j;
            float2 bv = *reinterpret_cast<const float2*>(bb + 2*p);
            #pragma unroll
            for (int i=0;i<16;i++){
                float2 a = u2f(acc[i][j]);
                float2* hp = reinterpret_cast<float2*>(hs + (r0+i)*512 + 2*p);
                float2 hv = *hp;
                *hp = make_float2(hv.x + lrelu(a.x + bv.x),
                                  hv.y + lrelu(a.y + bv.y));
            }
        }
    }
}

// ---------------------------------------------------------------------------
// Main kernel: 32 (window,channel) rows per CTA, full MLP chain in SMEM.
// Warp mapping: wr = wid&1 -> rows 16*wr..+15;  wc = wid>>2.. col group.
// ---------------------------------------------------------------------------
__global__ void __launch_bounds__(NTHR, 1)
main_kernel(const float* __restrict__ w_in, const float* __restrict__ b_in,
            const float* __restrict__ w1a, const float* __restrict__ b1a,
            const float* __restrict__ w1b, const float* __restrict__ b1b,
            const float* __restrict__ w2a, const float* __restrict__ b2a,
            const float* __restrict__ w2b, const float* __restrict__ b2b,
            const float* __restrict__ w_out, const float* __restrict__ b_out)
{
    extern __shared__ float smf[];
    float* xs = smf;               // 32*36  = 1152 floats
    float* hs = smf + 1152;        // 32*512 = 16384
    float* rs = hs + 16384;        // 32*256 = 8192
    float* wb = rs + 8192;         // up to 32*514 = 16448
    int tid = threadIdx.x, wid = tid >> 5, tc = tid & 31;
    int wr = wid & 1, wc = wid >> 1;
    int r0 = 16*wr;
    int m0 = blockIdx.x * 32;

    // load x window tile: xs[r][t] = d6[n+t][c] for m = m0+r
    for (int e = tid; e < 32*32; e += NTHR){
        int rrow = e & 31, t = e >> 5;
        int m = m0 + rrow; if (m >= MROWS) m = MROWS - 1;
        int n = m / CHANS, c = m - n*CHANS;
        xs[rrow*36 + t] = g_d6[(n + t)*CHANS + c];
    }

    // GEMM1: hs = lrelu(xs(32x32) @ w_in^T(->512) + b_in),  PPT=2
    {
        int pbase = tc + 64*wc;
        ull acc[16][2];
        #pragma unroll
        for (int i=0;i<16;i++){ acc[i][0] = 0ull; acc[i][1] = 0ull; }
        __syncthreads();
        stage_w<512,32>(w_in, 0, wb);
        __syncthreads();
        mma_cp<16,2,512>(xs, 36, wb, acc, r0, pbase);
        #pragma unroll
        for (int j=0;j<2;j++){
            int p = pbase + 32*j;
            float2 bv = *reinterpret_cast<const float2*>(b_in + 2*p);
            #pragma unroll
            for (int i=0;i<16;i++){
                float2 a = u2f(acc[i][j]);
                *reinterpret_cast<float2*>(hs + (r0+i)*512 + 2*p) =
                    make_float2(lrelu(a.x + bv.x), lrelu(a.y + bv.y));
            }
        }
    }

    resblock(hs, rs, wb, w1a, b1a, w1b, b1b, r0, wc, tc);
    resblock(hs, rs, wb, w2a, b2a, w2b, b2b, r0, wc, tc);

    // GEMM6: y = hs(32x512) @ w_out^T(->32) + b_out -> g_y
    // rows 4*wid per warp; lanes 0..15 own col pairs (16..31 duplicate).
    {
        int pbase = tc & 15;
        ull acc[4][1];
        #pragma unroll
        for (int i=0;i<4;i++) acc[i][0] = 0ull;
        for (int k0 = 0; k0 < 512; k0 += 32){
            __syncthreads();
            stage_w<32,512>(w_out, k0, wb);
            __syncthreads();
            mma_cp<4,1,32>(hs + k0, 512, wb, acc, 4*wid, pbase);
        }
        if (tc < 16){
            float2 bv = *reinterpret_cast<const float2*>(b_out + 2*pbase);
            #pragma unroll
            for (int i=0;i<4;i++){
                int m = m0 + 4*wid + i;
                if (m < MROWS){
                    float2 a = u2f(acc[i][0]);
                    *reinterpret_cast<float2*>(g_y + m*WINL + 2*pbase) =
                        make_float2(a.x + bv.x, a.y + bv.y);
                }
            }
        }
    }
}

// ---------------------------------------------------------------------------
// Stage C: overlap-average + 6D -> rotation matrix -> axis-angle
// ---------------------------------------------------------------------------
__global__ void finalize_kernel(float* __restrict__ out){
    int idx = blockIdx.x*blockDim.x + threadIdx.x;
    if (idx >= LFRM*24) return;
    int t = idx/24, j = idx - 24*t;
    int lo = t - 31; if (lo < 0) lo = 0;
    int hi = t;      if (hi > NWIN-1) hi = NWIN-1;
    float s0=0,s1=0,s2=0,s3=0,s4=0,s5=0;
    for (int n = lo; n <= hi; n++){
        const float* yy = g_y + (n*CHANS + 6*j)*WINL + (t - n);
        s0 += yy[0];      s1 += yy[WINL];   s2 += yy[2*WINL];
        s3 += yy[3*WINL]; s4 += yy[4*WINL]; s5 += yy[5*WINL];
    }
    float inv = 1.0f / (float)(hi - lo + 1);
    float a1x=s0*inv, a1y=s1*inv, a1z=s2*inv;
    float a2x=s3*inv, a2y=s4*inv, a2z=s5*inv;
    float n1 = sqrtf(a1x*a1x + a1y*a1y + a1z*a1z);
    float i1 = 1.0f / fmaxf(n1, 1e-8f);
    float b1x=a1x*i1, b1y=a1y*i1, b1z=a1z*i1;
    float d = b1x*a2x + b1y*a2y + b1z*a2z;
    float px = a2x - d*b1x, py = a2y - d*b1y, pz = a2z - d*b1z;
    float n2 = sqrtf(px*px + py*py + pz*pz);
    float i2 = 1.0f / fmaxf(n2, 1e-8f);
    float b2x=px*i2, b2y=py*i2, b2z=pz*i2;
    float b3x = b1y*b2z - b1z*b2y;
    float b3y = b1z*b2x - b1x*b2z;
    float b3z = b1x*b2y - b1y*b2x;
    float trc  = b1x + b2y + b3z;
    float cosv = (trc - 1.0f)*0.5f;
    cosv = fminf(fmaxf(cosv, -1.0f + 1e-6f), 1.0f - 1e-6f);
    float ang  = acosf(cosv);
    float sinv = sqrtf(fmaxf(1.0f - cosv*cosv, 1e-12f));
    float sc   = ang / (2.0f*sinv);
    out[t*72 + 3*j    ] = sc*(b3y - b2z);
    out[t*72 + 3*j + 1] = sc*(b1z - b3x);
    out[t*72 + 3*j + 2] = sc*(b2x - b1y);
}

// ---------------------------------------------------------------------------
extern "C" void kernel_launch(void* const* d_in, const int* in_sizes, int n_in,
                              void* d_out, int out_size){
    const float* dp    = (const float*)d_in[0];
    const float* w_in  = (const float*)d_in[1];
    const float* b_in  = (const float*)d_in[2];
    const float* w1a   = (const float*)d_in[3];
    const float* b1a   = (const float*)d_in[4];
    const float* w1b   = (const float*)d_in[5];
    const float* b1b   = (const float*)d_in[6];
    const float* w2a   = (const float*)d_in[7];
    const float* b2a   = (const float*)d_in[8];
    const float* w2b   = (const float*)d_in[9];
    const float* b2b   = (const float*)d_in[10];
    const float* w_out = (const float*)d_in[11];
    const float* b_out = (const float*)d_in[12];
    float* out = (float*)d_out;

    const int SMEM = (1152 + 16384 + 8192 + 16448) * 4;  // 168704 B
    cudaFuncSetAttribute(main_kernel, cudaFuncAttributeMaxDynamicSharedMemorySize, SMEM);

    aa_to_d6_kernel<<<(LFRM*24 + 255)/256, 256>>>(dp);
    main_kernel<<<(MROWS + 31)/32, NTHR, SMEM>>>(w_in, b_in, w1a, b1a, w1b, b1b,
                                                 w2a, b2a, w2b, b2b, w_out, b_out);
    finalize_kernel<<<(LFRM*24 + 255)/256, 256>>>(out);
}

// round 3
// speedup vs baseline: 1.3014x; 1.1088x over previous
#include <cuda_runtime.h>

#define SLOPE 0.1f
#define LFRM  1024
#define CHANS 144
#define WINL  32
#define NWIN  993                 // (1024 - 32)/1 + 1
#define MROWS (NWIN*CHANS)        // 142992 = 48 * 2979
#define MT    48                  // rows per CTA
#define NCTA  (MROWS/MT)          // 2979
#define NTHR  384

typedef unsigned long long ull;

// scratch (no cudaMalloc allowed)
__device__ float g_d6[LFRM*CHANS];        // 1024 x 144
__device__ float g_y[MROWS*WINL];         // per-window outputs, [m][w]

__device__ __forceinline__ float lrelu(float x){ return x >= 0.0f ? x : SLOPE*x; }

// packed f32x2 helpers (Blackwell FFMA2 path)
__device__ __forceinline__ void fma2(ull& d, ull a, ull b){
    asm("fma.rn.f32x2 %0, %1, %2, %0;" : "+l"(d) : "l"(a), "l"(b));
}
__device__ __forceinline__ ull dup2(float x){
    ull r; asm("mov.b64 %0, {%1, %1};" : "=l"(r) : "f"(x)); return r;
}
__device__ __forceinline__ float2 u2f(ull v){
    float2 f; asm("mov.b64 {%0, %1}, %2;" : "=f"(f.x), "=f"(f.y) : "l"(v)); return f;
}

// ---------------------------------------------------------------------------
// Stage A: axis-angle -> rotation matrix -> 6D (first two rows)
// ---------------------------------------------------------------------------
__global__ void aa_to_d6_kernel(const float* __restrict__ dp){
    int idx = blockIdx.x*blockDim.x + threadIdx.x;
    if (idx >= LFRM*24) return;
    int t = idx/24, j = idx - 24*t;
    float x = dp[t*72+3*j], y = dp[t*72+3*j+1], z = dp[t*72+3*j+2];
    float ang = sqrtf(x*x + y*y + z*z);
    float inv = 1.0f / fmaxf(ang, 1e-8f);
    x *= inv; y *= inv; z *= inv;
    float s = sinf(ang), c = cosf(ang);
    float C = 1.0f - c;
    float* o = g_d6 + t*CHANS + 6*j;
    o[0] = c + x*x*C;      o[1] = x*y*C - z*s;   o[2] = x*z*C + y*s;
    o[3] = y*x*C + z*s;    o[4] = c + y*y*C;     o[5] = y*z*C - x*s;
}

// ---------------------------------------------------------------------------
// Weight staging: W row-major [N][KF] -> wb k-major [32][NW+2]
// ---------------------------------------------------------------------------
template<int NW, int KF>
__device__ __forceinline__ void stage_w(const float* __restrict__ W, int k0,
                                        float* __restrict__ wb){
    const int NWP = NW + 2;
    for (int e = threadIdx.x; e < NW*8; e += NTHR){
        int n = e >> 3, u = e & 7;
        float4 v = *reinterpret_cast<const float4*>(W + n*KF + k0 + 4*u);
        wb[(4*u  )*NWP + n] = v.x;
        wb[(4*u+1)*NWP + n] = v.y;
        wb[(4*u+2)*NWP + n] = v.z;
        wb[(4*u+3)*NWP + n] = v.w;
    }
}

// ---------------------------------------------------------------------------
// One K=32 chunk of C[MT][NW] += A[MT][32] @ Wchunk^T with packed FFMA2.
// acc[i][j]: f32x2 over adjacent output cols of pair p = pbase + 32*j.
// Rows r0..r0+RPT-1 per thread; rows uniform per warp (A loads broadcast).
// ---------------------------------------------------------------------------
template<int RPT, int CP, int NW>
__device__ __forceinline__ void mma_cp(const float* __restrict__ A, int astr,
                                       const float* __restrict__ wb,
                                       ull (&acc)[RPT][CP], int r0, int pbase){
    const int NWP = NW + 2;
    constexpr int GR = RPT < 8 ? RPT : 8;
    #pragma unroll
    for (int h = 0; h < RPT/GR; h++){
        const float* a0 = A + (r0 + GR*h)*astr;
        #pragma unroll
        for (int k4 = 0; k4 < 32; k4 += 4){
            float4 av[GR];
            #pragma unroll
            for (int i = 0; i < GR; i++)
                av[i] = *reinterpret_cast<const float4*>(a0 + i*astr + k4);
            #pragma unroll
            for (int kk = 0; kk < 4; kk++){
                const ull* bp = reinterpret_cast<const ull*>(wb + (k4+kk)*NWP);
                ull b[CP];
                #pragma unroll
                for (int j = 0; j < CP; j++) b[j] = bp[pbase + 32*j];
                #pragma unroll
                for (int i = 0; i < GR; i++){
                    float as = (kk==0) ? av[i].x : (kk==1) ? av[i].y
                             : (kk==2) ? av[i].z : av[i].w;
                    ull ad = dup2(as);
                    #pragma unroll
                    for (int j = 0; j < CP; j++) fma2(acc[GR*h+i][j], ad, b[j]);
                }
            }
        }
    }
}

// ---------------------------------------------------------------------------
// One residual block: rs = lrelu(hs @ wa^T + ba); hs += lrelu(rs @ wbm^T + bb)
// ---------------------------------------------------------------------------
__device__ __forceinline__ void resblock(float* hs, float* rs, float* wb,
    const float* __restrict__ wa,  const float* __restrict__ ba,
    const float* __restrict__ wbm, const float* __restrict__ bb,
    int wid, int tc, int r0_512, int pb_512)
{
    {   // hs(48x512) @ (256x512)^T -> rs 48x256.  12 rowgroups x 1 colgroup: RPT=4, CP=4
        int r0 = 4*wid, pbase = tc;
        ull acc[4][4];
        #pragma unroll
        for (int i=0;i<4;i++){
            #pragma unroll
            for (int j=0;j<4;j++) acc[i][j] = 0ull;
        }
        for (int k0 = 0; k0 < 512; k0 += 32){
            __syncthreads();
            stage_w<256,512>(wa, k0, wb);
            __syncthreads();
            mma_cp<4,4,256>(hs + k0, 512, wb, acc, r0, pbase);
        }
        #pragma unroll
        for (int j=0;j<4;j++){
            int p = pbase + 32*j;
            float2 bv = *reinterpret_cast<const float2*>(ba + 2*p);
            #pragma unroll
            for (int i=0;i<4;i++){
                float2 a = u2f(acc[i][j]);
                *reinterpret_cast<float2*>(rs + (r0+i)*256 + 2*p) =
                    make_float2(lrelu(a.x + bv.x), lrelu(a.y + bv.y));
            }
        }
    }
    {   // rs(48x256) @ (512x256)^T -> residual into hs 48x512.  RPT=8, CP=4
        ull acc[8][4];
        #pragma unroll
        for (int i=0;i<8;i++){
            #pragma unroll
            for (int j=0;j<4;j++) acc[i][j] = 0ull;
        }
        for (int k0 = 0; k0 < 256; k0 += 32){
            __syncthreads();
            stage_w<512,256>(wbm, k0, wb);
            __syncthreads();
            mma_cp<8,4,512>(rs + k0, 256, wb, acc, r0_512, pb_512);
        }
        #pragma unroll
        for (int j=0;j<4;j++){
            int p = pb_512 + 32*j;
            float2 bv = *reinterpret_cast<const float2*>(bb + 2*p);
            #pragma unroll
            for (int i=0;i<8;i++){
                float2 a = u2f(acc[i][j]);
                float2* hp = reinterpret_cast<float2*>(hs + (r0_512+i)*512 + 2*p);
                float2 hv = *hp;
                *hp = make_float2(hv.x + lrelu(a.x + bv.x),
                                  hv.y + lrelu(a.y + bv.y));
            }
        }
    }
}

// ---------------------------------------------------------------------------
// Main kernel: 48 rows per CTA, 384 threads, full MLP chain in SMEM.
// N=512 GEMMs: 6 rowgroups (8 rows) x 2 colgroups (128 pairs).
// N=256 GEMMs: 12 rowgroups (4 rows) x 1 colgroup (128 pairs).
// ---------------------------------------------------------------------------
__global__ void __launch_bounds__(NTHR, 1)
main_kernel(const float* __restrict__ w_in, const float* __restrict__ b_in,
            const float* __restrict__ w1a, const float* __restrict__ b1a,
            const float* __restrict__ w1b, const float* __restrict__ b1b,
            const float* __restrict__ w2a, const float* __restrict__ b2a,
            const float* __restrict__ w2b, const float* __restrict__ b2b,
            const float* __restrict__ w_out, const float* __restrict__ b_out)
{
    extern __shared__ float smf[];
    float* xs = smf;                 // 48*36   = 1728
    float* hs = smf + 1728;          // 48*512  = 24576
    float* rs = hs + 24576;          // 48*256  = 12288
    float* wb = rs + 12288;          // 32*514  = 16448
    int tid = threadIdx.x, wid = tid >> 5, tc = tid & 31;
    int rg = wid % 6, wc = wid / 6;        // N=512 mapping
    int r0_512 = 8*rg, pb_512 = 128*wc + tc;
    int m0 = blockIdx.x * MT;

    // load x window tile: xs[r][t] = d6[n+t][c] for m = m0+r
    for (int e = tid; e < MT*32; e += NTHR){
        int rrow = e % MT, t = e / MT;
        int m = m0 + rrow;
        int n = m / CHANS, c = m - n*CHANS;
        xs[rrow*36 + t] = g_d6[(n + t)*CHANS + c];
    }

    // GEMM1: hs = lrelu(xs(48x32) @ w_in^T(->512) + b_in)
    {
        ull acc[8][4];
        #pragma unroll
        for (int i=0;i<8;i++){
            #pragma unroll
            for (int j=0;j<4;j++) acc[i][j] = 0ull;
        }
        __syncthreads();
        stage_w<512,32>(w_in, 0, wb);
        __syncthreads();
        mma_cp<8,4,512>(xs, 36, wb, acc, r0_512, pb_512);
        #pragma unroll
        for (int j=0;j<4;j++){
            int p = pb_512 + 32*j;
            float2 bv = *reinterpret_cast<const float2*>(b_in + 2*p);
            #pragma unroll
            for (int i=0;i<8;i++){
                float2 a = u2f(acc[i][j]);
                *reinterpret_cast<float2*>(hs + (r0_512+i)*512 + 2*p) =
                    make_float2(lrelu(a.x + bv.x), lrelu(a.y + bv.y));
            }
        }
    }

    resblock(hs, rs, wb, w1a, b1a, w1b, b1b, wid, tc, r0_512, pb_512);
    resblock(hs, rs, wb, w2a, b2a, w2b, b2b, wid, tc, r0_512, pb_512);

    // GEMM6: y = hs(48x512) @ w_out^T(->32) + b_out -> g_y
    // warp w: rows 4w..4w+3; lanes 0..15 own one col pair each.
    {
        int pbase = tc & 15;
        ull acc[4][1];
        #pragma unroll
        for (int i=0;i<4;i++) acc[i][0] = 0ull;
        for (int k0 = 0; k0 < 512; k0 += 32){
            __syncthreads();
            stage_w<32,512>(w_out, k0, wb);
            __syncthreads();
            mma_cp<4,1,32>(hs + k0, 512, wb, acc, 4*wid, pbase);
        }
        if (tc < 16){
            float2 bv = *reinterpret_cast<const float2*>(b_out + 2*pbase);
            #pragma unroll
            for (int i=0;i<4;i++){
                int m = m0 + 4*wid + i;
                float2 a = u2f(acc[i][0]);
                *reinterpret_cast<float2*>(g_y + m*WINL + 2*pbase) =
                    make_float2(a.x + bv.x, a.y + bv.y);
            }
        }
    }
}

// ---------------------------------------------------------------------------
// Stage C: overlap-average + 6D -> rotation matrix -> axis-angle
// ---------------------------------------------------------------------------
__global__ void finalize_kernel(float* __restrict__ out){
    int idx = blockIdx.x*blockDim.x + threadIdx.x;
    if (idx >= LFRM*24) return;
    int t = idx/24, j = idx - 24*t;
    int lo = t - 31; if (lo < 0) lo = 0;
    int hi = t;      if (hi > NWIN-1) hi = NWIN-1;
    float s0=0,s1=0,s2=0,s3=0,s4=0,s5=0;
    for (int n = lo; n <= hi; n++){
        const float* yy = g_y + (n*CHANS + 6*j)*WINL + (t - n);
        s0 += yy[0];      s1 += yy[WINL];   s2 += yy[2*WINL];
        s3 += yy[3*WINL]; s4 += yy[4*WINL]; s5 += yy[5*WINL];
    }
    float inv = 1.0f / (float)(hi - lo + 1);
    float a1x=s0*inv, a1y=s1*inv, a1z=s2*inv;
    float a2x=s3*inv, a2y=s4*inv, a2z=s5*inv;
    float n1 = sqrtf(a1x*a1x + a1y*a1y + a1z*a1z);
    float i1 = 1.0f / fmaxf(n1, 1e-8f);
    float b1x=a1x*i1, b1y=a1y*i1, b1z=a1z*i1;
    float d = b1x*a2x + b1y*a2y + b1z*a2z;
    float px = a2x - d*b1x, py = a2y - d*b1y, pz = a2z - d*b1z;
    float n2 = sqrtf(px*px + py*py + pz*pz);
    float i2 = 1.0f / fmaxf(n2, 1e-8f);
    float b2x=px*i2, b2y=py*i2, b2z=pz*i2;
    float b3x = b1y*b2z - b1z*b2y;
    float b3y = b1z*b2x - b1x*b2z;
    float b3z = b1x*b2y - b1y*b2x;
    float trc  = b1x + b2y + b3z;
    float cosv = (trc - 1.0f)*0.5f;
    cosv = fminf(fmaxf(cosv, -1.0f + 1e-6f), 1.0f - 1e-6f);
    float ang  = acosf(cosv);
    float sinv = sqrtf(fmaxf(1.0f - cosv*cosv, 1e-12f));
    float sc   = ang / (2.0f*sinv);
    out[t*72 + 3*j    ] = sc*(b3y - b2z);
    out[t*72 + 3*j + 1] = sc*(b1z - b3x);
    out[t*72 + 3*j + 2] = sc*(b2x - b1y);
}

// ---------------------------------------------------------------------------
extern "C" void kernel_launch(void* const* d_in, const int* in_sizes, int n_in,
                              void* d_out, int out_size){
    const float* dp    = (const float*)d_in[0];
    const float* w_in  = (const float*)d_in[1];
    const float* b_in  = (const float*)d_in[2];
    const float* w1a   = (const float*)d_in[3];
    const float* b1a   = (const float*)d_in[4];
    const float* w1b   = (const float*)d_in[5];
    const float* b1b   = (const float*)d_in[6];
    const float* w2a   = (const float*)d_in[7];
    const float* b2a   = (const float*)d_in[8];
    const float* w2b   = (const float*)d_in[9];
    const float* b2b   = (const float*)d_in[10];
    const float* w_out = (const float*)d_in[11];
    const float* b_out = (const float*)d_in[12];
    float* out = (float*)d_out;

    const int SMEM = (1728 + 24576 + 12288 + 16448) * 4;  // 220160 B
    cudaFuncSetAttribute(main_kernel, cudaFuncAttributeMaxDynamicSharedMemorySize, SMEM);

    aa_to_d6_kernel<<<(LFRM*24 + 255)/256, 256>>>(dp);
    main_kernel<<<NCTA, NTHR, SMEM>>>(w_in, b_in, w1a, b1a, w1b, b1b,
                                      w2a, b2a, w2b, b2b, w_out, b_out);
    finalize_kernel<<<(LFRM*24 + 255)/256, 256>>>(out);
}

// round 5
// speedup vs baseline: 1.8122x; 1.3925x over previous
#include <cuda_runtime.h>

#define SLOPE 0.1f
#define LFRM  1024
#define CHANS 144
#define WINL  32
#define NWIN  993
#define MROWS (NWIN*CHANS)        // 142992
#define MTILES 1118               // ceil(142992/128)
#define MPAD  (MTILES*128)        // 143104

typedef unsigned int u32;

// ---------------- device scratch (no cudaMalloc allowed) -------------------
__device__ float g_d6[LFRM*CHANS];
__device__ float g_h[(size_t)MPAD*512];
__device__ float g_r[(size_t)MPAD*256];
__device__ float g_y[(size_t)MROWS*WINL];
// tf32 hi/lo weight images, per-layer [K][N] row-major (k-major)
#define WIMG 557056
__device__ __align__(16) u32 g_whi[WIMG];
__device__ __align__(16) u32 g_wlo[WIMG];
#define Q1 0
#define Q2 16384
#define Q3 147456
#define Q4 278528
#define Q5 409600
#define Q6 540672

__device__ __forceinline__ float lrelu(float x){ return x >= 0.0f ? x : SLOPE*x; }

// ---------------- PTX helpers ----------------------------------------------
__device__ __forceinline__ u32 smem_u32(const void* p){
    u32 a; asm("{ .reg .u64 t; cvta.to.shared.u64 t, %1; cvt.u32.u64 %0, t; }" : "=r"(a) : "l"(p));
    return a;
}
__device__ __forceinline__ u32 tf32r(float x){
    u32 r; asm("cvt.rna.tf32.f32 %0, %1;" : "=r"(r) : "f"(x)); return r;
}
__device__ __forceinline__ void mma_tf32(float* d, const u32* a, u32 b0, u32 b1){
    asm volatile(
        "mma.sync.aligned.m16n8k8.row.col.f32.tf32.tf32.f32 "
        "{%0,%1,%2,%3}, {%4,%5,%6,%7}, {%8,%9}, {%0,%1,%2,%3};"
        : "+f"(d[0]), "+f"(d[1]), "+f"(d[2]), "+f"(d[3])
        : "r"(a[0]), "r"(a[1]), "r"(a[2]), "r"(a[3]), "r"(b0), "r"(b1));
}
#define CP16(dst, src) asm volatile("cp.async.cg.shared.global [%0], [%1], 16;" :: "r"(dst), "l"(src))
#define CP4(dst, src)  asm volatile("cp.async.ca.shared.global [%0], [%1], 4;"  :: "r"(dst), "l"(src))
#define CP_COMMIT()    asm volatile("cp.async.commit_group;" ::: "memory")
#define CP_WAIT(n)     asm volatile("cp.async.wait_group %0;" :: "n"(n) : "memory")

// ---------------------------------------------------------------------------
// Stage A: axis-angle -> 6D
// ---------------------------------------------------------------------------
__global__ void aa_to_d6_kernel(const float* __restrict__ dp){
    int idx = blockIdx.x*blockDim.x + threadIdx.x;
    if (idx >= LFRM*24) return;
    int t = idx/24, j = idx - 24*t;
    float x = dp[t*72+3*j], y = dp[t*72+3*j+1], z = dp[t*72+3*j+2];
    float ang = sqrtf(x*x + y*y + z*z);
    float inv = 1.0f / fmaxf(ang, 1e-8f);
    x *= inv; y *= inv; z *= inv;
    float s = sinf(ang), c = cosf(ang);
    float C = 1.0f - c;
    float* o = g_d6 + t*CHANS + 6*j;
    o[0] = c + x*x*C;      o[1] = x*y*C - z*s;   o[2] = x*z*C + y*s;
    o[3] = y*x*C + z*s;    o[4] = c + y*y*C;     o[5] = y*z*C - x*s;
}

// ---------------------------------------------------------------------------
// Weight prep: W[N][K] row-major -> tf32 hi/lo images Wimg[K][N]
// ---------------------------------------------------------------------------
__global__ void prep_kernel(const float* __restrict__ w_in, const float* __restrict__ w1a,
                            const float* __restrict__ w1b, const float* __restrict__ w2a,
                            const float* __restrict__ w2b, const float* __restrict__ w_out){
    int idx = blockIdx.x*blockDim.x + threadIdx.x;
    if (idx >= WIMG) return;
    int base, N, K; const float* W;
    if      (idx < Q2){ base=Q1; N=512; K=32;  W=w_in;  }
    else if (idx < Q3){ base=Q2; N=256; K=512; W=w1a;   }
    else if (idx < Q4){ base=Q3; N=512; K=256; W=w1b;   }
    else if (idx < Q5){ base=Q4; N=256; K=512; W=w2a;   }
    else if (idx < Q6){ base=Q5; N=512; K=256; W=w2b;   }
    else              { base=Q6; N=32;  K=512; W=w_out; }
    int e = idx - base;
    int k = e / N, n = e - k*N;
    float v = W[n*K + k];
    u32 hi = tf32r(v);
    float lo = v - __uint_as_float(hi);
    g_whi[idx] = hi;
    g_wlo[idx] = tf32r(lo);
}

// ---------------------------------------------------------------------------
// GEMM: C[128 x NT per CTA] = act(A @ W^T + b) [+res], 3xTF32 on mma.sync.
// 512 threads, warp grid MW x NW. cp.async double-buffered K=32 chunks.
// ---------------------------------------------------------------------------
template<int KTOT, int NT, int NFULL, int MW, int NW, bool GATHER, bool RELU, bool RES>
__global__ void __launch_bounds__(512, 1)
gemm_tc(const float* __restrict__ A, int ldA,
        const float* __restrict__ bias,
        float* __restrict__ C, int ldC,
        const float* __restrict__ res,
        const u32* __restrict__ Wh, const u32* __restrict__ Wl)
{
    constexpr int KC = 32, NCH = KTOT/32;
    constexpr int WM = 128/MW, WN = NT/NW, MF = WM/16, NF = WN/8;
    constexpr int NTP = NT + 8, ASTR = 36;
    constexpr int AELE = 128*ASTR, BELE = KC*NTP;

    extern __shared__ float sm[];
    float* Ab[2] = { sm, sm + AELE };
    u32* BHp[2]; u32* BLp[2];
    BHp[0] = (u32*)(sm + 2*AELE); BLp[0] = BHp[0] + BELE;
    BHp[1] = BLp[0] + BELE;       BLp[1] = BHp[1] + BELE;

    const int tid = threadIdx.x, lane = tid & 31, wid = tid >> 5;
    const int gid = lane >> 2, tig = lane & 3;
    const int warp_n = wid % NW, warp_m = wid / NW;
    const int m0 = blockIdx.x * 128;
    const int col0 = blockIdx.y * NT;

    float acc[MF][NF][4];
    #pragma unroll
    for (int i = 0; i < MF; i++)
        #pragma unroll
        for (int j = 0; j < NF; j++)
            #pragma unroll
            for (int q = 0; q < 4; q++) acc[i][j][q] = 0.0f;

    auto stage = [&](int c, int b){
        if (GATHER){
            for (int idx = tid; idx < 128*KC; idx += 512){
                int r = idx >> 5, k = idx & 31;
                int m = m0 + r; if (m >= MROWS) m = MROWS - 1;
                int n = m / CHANS, ch = m - n*CHANS;
                CP4(smem_u32(&Ab[b][r*ASTR + k]), g_d6 + (n + k)*CHANS + ch);
            }
        } else {
            for (int idx = tid; idx < 128*8; idx += 512){
                int r = idx >> 3, q = idx & 7;
                CP16(smem_u32(&Ab[b][r*ASTR + 4*q]),
                     A + (size_t)(m0 + r)*ldA + c*KC + 4*q);
            }
        }
        constexpr int QN = NT/4;
        for (int idx = tid; idx < 2*KC*QN; idx += 512){
            int q = idx % QN, kr = (idx / QN) % KC, im = idx / (QN*KC);
            const u32* src = (im ? Wl : Wh) + (size_t)(c*KC + kr)*NFULL + col0 + 4*q;
            u32* dst = (im ? BLp[b] : BHp[b]) + kr*NTP + 4*q;
            CP16(smem_u32(dst), src);
        }
    };

    stage(0, 0); CP_COMMIT();
    if (NCH > 1){ stage(1, 1); CP_COMMIT(); }

    for (int c = 0; c < NCH; c++){
        if (c == NCH-1) { CP_WAIT(0); } else { CP_WAIT(1); }
        __syncthreads();
        int b = c & 1;
        const float* As = Ab[b];
        const u32* BHs = BHp[b];
        const u32* BLs = BLp[b];
        #pragma unroll
        for (int ks = 0; ks < KC/8; ks++){
            u32 ah[MF][4], al[MF][4];
            #pragma unroll
            for (int mf = 0; mf < MF; mf++){
                int r0 = warp_m*WM + mf*16 + gid;
                int kk = ks*8 + tig;
                float x0 = As[r0*ASTR + kk];
                float x1 = As[(r0+8)*ASTR + kk];
                float x2 = As[r0*ASTR + kk + 4];
                float x3 = As[(r0+8)*ASTR + kk + 4];
                ah[mf][0] = tf32r(x0); al[mf][0] = tf32r(x0 - __uint_as_float(ah[mf][0]));
                ah[mf][1] = tf32r(x1); al[mf][1] = tf32r(x1 - __uint_as_float(ah[mf][1]));
                ah[mf][2] = tf32r(x2); al[mf][2] = tf32r(x2 - __uint_as_float(ah[mf][2]));
                ah[mf][3] = tf32r(x3); al[mf][3] = tf32r(x3 - __uint_as_float(ah[mf][3]));
            }
            #pragma unroll
            for (int nf = 0; nf < NF; nf++){
                int cn = warp_n*WN + nf*8 + gid;
                int kr = ks*8 + tig;
                u32 bh0 = BHs[kr*NTP + cn], bh1 = BHs[(kr+4)*NTP + cn];
                u32 bl0 = BLs[kr*NTP + cn], bl1 = BLs[(kr+4)*NTP + cn];
                #pragma unroll
                for (int mf = 0; mf < MF; mf++){
                    mma_tf32(acc[mf][nf], ah[mf], bh0, bh1);
                    mma_tf32(acc[mf][nf], ah[mf], bl0, bl1);
                    mma_tf32(acc[mf][nf], al[mf], bh0, bh1);
                }
            }
        }
        if (c + 2 < NCH){
            __syncthreads();
            stage(c + 2, b); CP_COMMIT();
        }
    }

    // ---- epilogue ----
    #pragma unroll
    for (int mf = 0; mf < MF; mf++){
        int row = m0 + warp_m*WM + mf*16 + gid;
        #pragma unroll
        for (int nf = 0; nf < NF; nf++){
            int cn = col0 + warp_n*WN + nf*8 + 2*tig;
            float2 bv = *reinterpret_cast<const float2*>(bias + cn);
            float v0x = acc[mf][nf][0] + bv.x, v0y = acc[mf][nf][1] + bv.y;
            float v1x = acc[mf][nf][2] + bv.x, v1y = acc[mf][nf][3] + bv.y;
            if (RELU){ v0x = lrelu(v0x); v0y = lrelu(v0y); v1x = lrelu(v1x); v1y = lrelu(v1y); }
            if (row < MROWS){
                if (RES){
                    float2 rv = *reinterpret_cast<const float2*>(res + (size_t)row*ldC + cn);
                    v0x += rv.x; v0y += rv.y;
                }
                *reinterpret_cast<float2*>(C + (size_t)row*ldC + cn) = make_float2(v0x, v0y);
            }
            if (row + 8 < MROWS){
                if (RES){
                    float2 rv = *reinterpret_cast<const float2*>(res + (size_t)(row+8)*ldC + cn);
                    v1x += rv.x; v1y += rv.y;
                }
                *reinterpret_cast<float2*>(C + (size_t)(row+8)*ldC + cn) = make_float2(v1x, v1y);
            }
        }
    }
}

// ---------------------------------------------------------------------------
// Stage C: overlap-average + 6D -> axis-angle
// ---------------------------------------------------------------------------
__global__ void finalize_kernel(float* __restrict__ out){
    int idx = blockIdx.x*blockDim.x + threadIdx.x;
    if (idx >= LFRM*24) return;
    int t = idx/24, j = idx - 24*t;
    int lo = t - 31; if (lo < 0) lo = 0;
    int hi = t;      if (hi > NWIN-1) hi = NWIN-1;
    float s0=0,s1=0,s2=0,s3=0,s4=0,s5=0;
    for (int n = lo; n <= hi; n++){
        const float* yy = g_y + ((size_t)n*CHANS + 6*j)*WINL + (t - n);
        s0 += yy[0];      s1 += yy[WINL];   s2 += yy[2*WINL];
        s3 += yy[3*WINL]; s4 += yy[4*WINL]; s5 += yy[5*WINL];
    }
    float inv = 1.0f / (float)(hi - lo + 1);
    float a1x=s0*inv, a1y=s1*inv, a1z=s2*inv;
    float a2x=s3*inv, a2y=s4*inv, a2z=s5*inv;
    float n1 = sqrtf(a1x*a1x + a1y*a1y + a1z*a1z);
    float i1 = 1.0f / fmaxf(n1, 1e-8f);
    float b1x=a1x*i1, b1y=a1y*i1, b1z=a1z*i1;
    float d = b1x*a2x + b1y*a2y + b1z*a2z;
    float px = a2x - d*b1x, py = a2y - d*b1y, pz = a2z - d*b1z;
    float n2 = sqrtf(px*px + py*py + pz*pz);
    float i2 = 1.0f / fmaxf(n2, 1e-8f);
    float b2x=px*i2, b2y=py*i2, b2z=pz*i2;
    float b3x = b1y*b2z - b1z*b2y;
    float b3y = b1z*b2x - b1x*b2z;
    float b3z = b1x*b2y - b1y*b2x;
    float trc  = b1x + b2y + b3z;
    float cosv = (trc - 1.0f)*0.5f;
    cosv = fminf(fmaxf(cosv, -1.0f + 1e-6f), 1.0f - 1e-6f);
    float ang  = acosf(cosv);
    float sinv = sqrtf(fmaxf(1.0f - cosv*cosv, 1e-12f));
    float sc   = ang / (2.0f*sinv);
    out[t*72 + 3*j    ] = sc*(b3y - b2z);
    out[t*72 + 3*j + 1] = sc*(b1z - b3x);
    out[t*72 + 3*j + 2] = sc*(b2x - b1y);
}

// ---------------------------------------------------------------------------
extern "C" void kernel_launch(void* const* d_in, const int* in_sizes, int n_in,
                              void* d_out, int out_size){
    const float* dp    = (const float*)d_in[0];
    const float* w_in  = (const float*)d_in[1];
    const float* b_in  = (const float*)d_in[2];
    const float* w1a   = (const float*)d_in[3];
    const float* b1a   = (const float*)d_in[4];
    const float* w1b   = (const float*)d_in[5];
    const float* b1b   = (const float*)d_in[6];
    const float* w2a   = (const float*)d_in[7];
    const float* b2a   = (const float*)d_in[8];
    const float* w2b   = (const float*)d_in[9];
    const float* b2b   = (const float*)d_in[10];
    const float* w_out = (const float*)d_in[11];
    const float* b_out = (const float*)d_in[12];
    float* out = (float*)d_out;

    float *p_h, *p_r, *p_y; u32 *p_wh, *p_wl;
    cudaGetSymbolAddress((void**)&p_h, g_h);
    cudaGetSymbolAddress((void**)&p_r, g_r);
    cudaGetSymbolAddress((void**)&p_y, g_y);
    cudaGetSymbolAddress((void**)&p_wh, g_whi);
    cudaGetSymbolAddress((void**)&p_wl, g_wlo);

    // smem: A 2*4608 + B 4*KC*NTP floats
    const int SM256 = (2*4608 + 4*32*264) * 4;   // 172032
    const int SM32  = (2*4608 + 4*32*40) * 4;    //  57344
    cudaFuncSetAttribute(gemm_tc<32, 256,512,4,4,true, true, false>, cudaFuncAttributeMaxDynamicSharedMemorySize, SM256);
    cudaFuncSetAttribute(gemm_tc<512,256,256,4,4,false,true, false>, cudaFuncAttributeMaxDynamicSharedMemorySize, SM256);
    cudaFuncSetAttribute(gemm_tc<256,256,512,4,4,false,true, true >, cudaFuncAttributeMaxDynamicSharedMemorySize, SM256);
    cudaFuncSetAttribute(gemm_tc<512,32, 32, 8,2,false,false,false>, cudaFuncAttributeMaxDynamicSharedMemorySize, SM32);

    prep_kernel<<<(WIMG + 255)/256, 256>>>(w_in, w1a, w1b, w2a, w2b, w_out);
    aa_to_d6_kernel<<<(LFRM*24 + 255)/256, 256>>>(dp);

    // L1: h = lrelu(x @ w_in^T + b_in)     [M,32 -> 512]
    gemm_tc<32,256,512,4,4,true,true,false><<<dim3(MTILES,2), 512, SM256>>>(
        nullptr, 0, b_in, p_h, 512, nullptr, p_wh + Q1, p_wl + Q1);
    // L2: r = lrelu(h @ w1a^T + b1a)       [M,512 -> 256]
    gemm_tc<512,256,256,4,4,false,true,false><<<dim3(MTILES,1), 512, SM256>>>(
        p_h, 512, b1a, p_r, 256, nullptr, p_wh + Q2, p_wl + Q2);
    // L3: h += lrelu(r @ w1b^T + b1b)      [M,256 -> 512]
    gemm_tc<256,256,512,4,4,false,true,true><<<dim3(MTILES,2), 512, SM256>>>(
        p_r, 256, b1b, p_h, 512, p_h, p_wh + Q3, p_wl + Q3);
    // L4
    gemm_tc<512,256,256,4,4,false,true,false><<<dim3(MTILES,1), 512, SM256>>>(
        p_h, 512, b2a, p_r, 256, nullptr, p_wh + Q4, p_wl + Q4);
    // L5
    gemm_tc<256,256,512,4,4,false,true,true><<<dim3(MTILES,2), 512, SM256>>>(
        p_r, 256, b2b, p_h, 512, p_h, p_wh + Q5, p_wl + Q5);
    // L6: y = h @ w_out^T + b_out          [M,512 -> 32]
    gemm_tc<512,32,32,8,2,false,false,false><<<dim3(MTILES,1), 512, SM32>>>(
        p_h, 512, b_out, p_y, 32, nullptr, p_wh + Q6, p_wl + Q6);

    finalize_kernel<<<(LFRM*24 + 255)/256, 256>>>(out);
}